// round 15
// baseline (speedup 1.0000x reference)
#include <cuda_runtime.h>
#include <cuda_fp16.h>
#include <cstdint>

#define N_NODES 50000
#define N_EDGES 800000
#define D 128
#define SU 136      // padded smem stride in halves

// ---------------------------------------------------------------------------
// Device scratch
// ---------------------------------------------------------------------------
__device__ int     g_cin[N_NODES];        // deg_in  - 1 (src counts)
__device__ int     g_cnt[N_NODES];        // deg_out - 1 (dst counts)
__device__ int     g_rowptr[N_NODES + 1];
__device__ int     g_cursor[N_NODES];
__device__ int     g_col[N_EDGES];
__device__ float   g_sout[N_NODES];       // rsqrt(deg_out)
__device__ __half  g_xsh[N_NODES * D];    // fp16( x * rsqrt(deg_in) )
__device__ __half  g_Wh[D * D];           // fp16(W), [j][k] row-major
__device__ int     g_bsum[256];           // per-block count sums (196 used)

#define ZB ((N_NODES + 255) / 256)        // 196
#define EPB ((N_EDGES / 2 + 255) / 256)   // 1563 edge-pair blocks
#define WB ((D * D + 255) / 256)          // 64
#define SB ((N_NODES * (D / 4) + 255) / 256)  // 6250

__device__ __forceinline__ uint32_t smem_u32(const void* p) {
    uint32_t a;
    asm("{ .reg .u64 t; cvta.to.shared.u64 t, %1; cvt.u32.u64 %0, t; }"
        : "=r"(a) : "l"(p));
    return a;
}

// Block-wide inclusive scan (256 threads) with warp shuffles; 2 barriers.
__device__ __forceinline__ int block_incl_scan256(int v, int* ws) {
    int lane = threadIdx.x & 31, w = threadIdx.x >> 5;
#pragma unroll
    for (int o = 1; o < 32; o <<= 1) {
        int t = __shfl_up_sync(0xffffffffu, v, o);
        if (lane >= o) v += t;
    }
    if (lane == 31) ws[w] = v;
    __syncthreads();
    if (w == 0) {
        int s = (lane < 8) ? ws[lane] : 0;
#pragma unroll
        for (int o = 1; o < 8; o <<= 1) {
            int t = __shfl_up_sync(0xffffffffu, s, o);
            if (lane >= o) s += t;
        }
        if (lane < 8) ws[lane] = s;
    }
    __syncthreads();
    if (w > 0) v += ws[w - 1];
    return v;
}

// ---------------------------------------------------------------------------
// Kernel 1: zero degree counters + fp16 W convert (disjoint block ranges)
// ---------------------------------------------------------------------------
__global__ __launch_bounds__(256) void zero_kernel(const float* __restrict__ Wm) {
    int bid = blockIdx.x;
    if (bid < ZB) {
        int i = bid * 256 + threadIdx.x;
        if (i < N_NODES) { g_cin[i] = 0; g_cnt[i] = 0; }
    } else {
        int i = (bid - ZB) * 256 + threadIdx.x;
        if (i < D * D) g_Wh[i] = __float2half(Wm[i]);
    }
}

// ---------------------------------------------------------------------------
// Kernel 2: degree counts, 2 edges per thread (int4)
// ---------------------------------------------------------------------------
__global__ __launch_bounds__(256) void degree_kernel(const int4* __restrict__ epairs) {
    int i = blockIdx.x * 256 + threadIdx.x;       // pair index
    if (i < N_EDGES / 2) {
        int4 p = epairs[i];
        atomicAdd(&g_cin[p.x], 1);
        atomicAdd(&g_cnt[p.y], 1);
        atomicAdd(&g_cin[p.z], 1);
        atomicAdd(&g_cnt[p.w], 1);
    }
}

// ---------------------------------------------------------------------------
// Kernel 3: scale + scanA (disjoint block ranges)
// ---------------------------------------------------------------------------
__global__ __launch_bounds__(256) void scale_scanA_kernel(const float* __restrict__ x) {
    int bid = blockIdx.x;
    if (bid < SB) {
        int i = bid * 256 + threadIdx.x;         // float4 index
        if (i < N_NODES * (D / 4)) {
            int row = i >> 5;
            float s = rsqrtf((float)(g_cin[row] + 1));
            float4 v = reinterpret_cast<const float4*>(x)[i];
            __half2 h0 = __floats2half2_rn(v.x * s, v.y * s);
            __half2 h1 = __floats2half2_rn(v.z * s, v.w * s);
            *reinterpret_cast<__half2*>(&g_xsh[(size_t)i * 4])     = h0;
            *reinterpret_cast<__half2*>(&g_xsh[(size_t)i * 4 + 2]) = h1;
            if ((i & 31) == 0) g_sout[row] = rsqrtf((float)(g_cnt[row] + 1));
        }
    } else {
        __shared__ int sh[8];
        int blk = bid - SB;
        int i = blk * 256 + threadIdx.x;
        int v = (i < N_NODES) ? g_cnt[i] : 0;
        int lane = threadIdx.x & 31, warp = threadIdx.x >> 5;
#pragma unroll
        for (int o = 16; o > 0; o >>= 1) v += __shfl_down_sync(0xffffffffu, v, o);
        if (lane == 0) sh[warp] = v;
        __syncthreads();
        if (warp == 0) {
            int w = (lane < 8) ? sh[lane] : 0;
#pragma unroll
            for (int o = 4; o > 0; o >>= 1) w += __shfl_down_sync(0xffffffffu, w, o);
            if (lane == 0) g_bsum[blk] = w;
        }
    }
}

// ---------------------------------------------------------------------------
// Kernel 4: fused scanB+scanC, shuffle scans
// ---------------------------------------------------------------------------
__global__ __launch_bounds__(256) void scanBC_kernel() {
    __shared__ int bs[256];
    __shared__ int ws[8];
    int t = threadIdx.x;

    int bv = (t < ZB) ? g_bsum[t] : 0;
    int sc = block_incl_scan256(bv, ws);
    bs[t] = sc;
    __syncthreads();
    int boff  = (blockIdx.x > 0) ? bs[blockIdx.x - 1] : 0;
    int total = bs[ZB - 1];

    int i = blockIdx.x * 256 + t;
    int v = (i < N_NODES) ? g_cnt[i] : 0;
    int sc2 = block_incl_scan256(v, ws);
    if (i < N_NODES) {
        int p = boff + sc2 - v;       // exclusive prefix
        g_rowptr[i] = p;
        g_cursor[i] = p;
    }
    if (blockIdx.x == 0 && t == 0) g_rowptr[N_NODES] = total;
}

// ---------------------------------------------------------------------------
// Kernel 5: fill CSR column array, 2 edges per thread (int4)
// ---------------------------------------------------------------------------
__global__ __launch_bounds__(256) void fill_kernel(const int4* __restrict__ epairs) {
    int i = blockIdx.x * 256 + threadIdx.x;       // pair index
    if (i < N_EDGES / 2) {
        int4 p = epairs[i];
        int pos0 = atomicAdd(&g_cursor[p.y], 1);
        g_col[pos0] = p.x;
        int pos1 = atomicAdd(&g_cursor[p.w], 1);
        g_col[pos1] = p.z;
    }
}

// ---------------------------------------------------------------------------
// Kernel 6: FUSED gather + tensor-core GEMM (mma.sync m16n8k16 f16).
//   256 threads / 8 warps / 128 rows (16/warp, private), 3 CTAs/SM.
//   Gather inner loop: pairwise __hadd2 in fp16, then fp32 accumulate
//   (-37% ALU issue vs per-edge cvt+fadd, no extra registers).
// ---------------------------------------------------------------------------
#define GEMM_ROWS 128
#define SMEM_W_HALVES (D * SU)                 // 17408
#define SMEM_U_HALVES (GEMM_ROWS * SU)         // 17408
#define SMEM_BYTES ((SMEM_W_HALVES + SMEM_U_HALVES) * 2)   // 69632

__global__ __launch_bounds__(256, 3) void fused_kernel(
    const float* __restrict__ b, float* __restrict__ out) {
    extern __shared__ __half smem[];
    __half* Ws = smem;                     // [128][SU]
    __half* Us = smem + SMEM_W_HALVES;     // [128][SU]

    int tid  = threadIdx.x;
    int lane = tid & 31;
    int warp = tid >> 5;
    int row0 = blockIdx.x * GEMM_ROWS;
    int r0   = warp * 16;                  // warp-local row base

    // ---- Stage W (coalesced uint4 = 8 halves), barrier BEFORE gather ----
    {
        const uint4* src = reinterpret_cast<const uint4*>(g_Wh);
        for (int t = tid; t < D * (D / 8); t += 256) {
            int row = t >> 4;
            int c8  = t & 15;
            uint4 v = src[t];
            *reinterpret_cast<uint4*>(&Ws[row * SU + c8 * 8]) = v;
        }
    }
    __syncthreads();

    // ---- Phase 1: warp-private gather of rows [16w, 16w+16) ----
    {
        const __half2* xs2 = reinterpret_cast<const __half2*>(g_xsh);
        int fo = lane * 2;                 // half2 index within row [0,64)
#pragma unroll 2
        for (int i = 0; i < 16; i++) {
            int node = row0 + r0 + i;
            float2 a0 = make_float2(0.f, 0.f);
            float2 a1 = make_float2(0.f, 0.f);
            if (node < N_NODES) {
                uint2 raw = *reinterpret_cast<const uint2*>(&xs2[(size_t)node * 64 + fo]);
                a0 = __half22float2(*reinterpret_cast<__half2*>(&raw.x));
                a1 = __half22float2(*reinterpret_cast<__half2*>(&raw.y));
                int s = g_rowptr[node];
                int e = g_rowptr[node + 1];
                int j = s;
                for (; j + 4 <= e; j += 4) {
                    int u0 = g_col[j + 0];
                    int u1 = g_col[j + 1];
                    int u2 = g_col[j + 2];
                    int u3 = g_col[j + 3];
                    uint2 q0 = *reinterpret_cast<const uint2*>(&xs2[(size_t)u0 * 64 + fo]);
                    uint2 q1 = *reinterpret_cast<const uint2*>(&xs2[(size_t)u1 * 64 + fo]);
                    uint2 q2 = *reinterpret_cast<const uint2*>(&xs2[(size_t)u2 * 64 + fo]);
                    uint2 q3 = *reinterpret_cast<const uint2*>(&xs2[(size_t)u3 * 64 + fo]);
                    // pairwise fp16 adds, then fp32 accumulate
                    __half2 sx0 = __hadd2(*reinterpret_cast<__half2*>(&q0.x),
                                          *reinterpret_cast<__half2*>(&q1.x));
                    __half2 sx1 = __hadd2(*reinterpret_cast<__half2*>(&q2.x),
                                          *reinterpret_cast<__half2*>(&q3.x));
                    __half2 sy0 = __hadd2(*reinterpret_cast<__half2*>(&q0.y),
                                          *reinterpret_cast<__half2*>(&q1.y));
                    __half2 sy1 = __hadd2(*reinterpret_cast<__half2*>(&q2.y),
                                          *reinterpret_cast<__half2*>(&q3.y));
                    float2 f;
                    f = __half22float2(sx0); a0.x += f.x; a0.y += f.y;
                    f = __half22float2(sx1); a0.x += f.x; a0.y += f.y;
                    f = __half22float2(sy0); a1.x += f.x; a1.y += f.y;
                    f = __half22float2(sy1); a1.x += f.x; a1.y += f.y;
                }
                for (; j < e; j++) {
                    int u = g_col[j];
                    uint2 q = *reinterpret_cast<const uint2*>(&xs2[(size_t)u * 64 + fo]);
                    float2 f;
                    f = __half22float2(*reinterpret_cast<__half2*>(&q.x)); a0.x += f.x; a0.y += f.y;
                    f = __half22float2(*reinterpret_cast<__half2*>(&q.y)); a1.x += f.x; a1.y += f.y;
                }
                float so = g_sout[node];
                a0.x *= so; a0.y *= so; a1.x *= so; a1.y *= so;
            }
            __half2 h0 = __floats2half2_rn(a0.x, a0.y);
            __half2 h1 = __floats2half2_rn(a1.x, a1.y);
            uint2 packed;
            packed.x = *reinterpret_cast<uint32_t*>(&h0);
            packed.y = *reinterpret_cast<uint32_t*>(&h1);
            *reinterpret_cast<uint2*>(&Us[(r0 + i) * SU + lane * 4]) = packed;
        }
    }
    __syncwarp();

    // ---- Phase 2: 16x128 = A(16x128) @ W^T, two 64-col halves ----
    int tr = lane & 7;
    int aRow  = r0 + tr + ((lane & 8) ? 8 : 0);
    int aKoff = (lane & 16) ? 8 : 0;
    uint32_t aBase = smem_u32(&Us[aRow * SU + aKoff]);
    int bTile = (lane >> 3) & 1;
    uint32_t bBase = smem_u32(&Ws[tr * SU + bTile * 8]);

    int rA = row0 + r0 + (lane >> 2);
    int rB = rA + 8;

#pragma unroll
    for (int half = 0; half < 2; half++) {
        float acc[8][4];
#pragma unroll
        for (int n8 = 0; n8 < 8; n8++)
#pragma unroll
            for (int q = 0; q < 4; q++) acc[n8][q] = 0.f;

#pragma unroll
        for (int ks = 0; ks < 8; ks++) {        // k = 16*ks
            uint32_t a0, a1, a2, a3;
            asm volatile(
                "ldmatrix.sync.aligned.m8n8.x4.shared.b16 {%0,%1,%2,%3}, [%4];"
                : "=r"(a0), "=r"(a1), "=r"(a2), "=r"(a3)
                : "r"(aBase + ks * 32));
#pragma unroll
            for (int n8 = 0; n8 < 8; n8++) {
                int nt = half * 8 + n8;
                uint32_t b0, b1;
                asm volatile(
                    "ldmatrix.sync.aligned.m8n8.x2.shared.b16 {%0,%1}, [%2];"
                    : "=r"(b0), "=r"(b1)
                    : "r"(bBase + nt * (8 * SU * 2) + ks * 32));
                asm volatile(
                    "mma.sync.aligned.m16n8k16.row.col.f32.f16.f16.f32 "
                    "{%0,%1,%2,%3}, {%4,%5,%6,%7}, {%8,%9}, {%0,%1,%2,%3};"
                    : "+f"(acc[n8][0]), "+f"(acc[n8][1]),
                      "+f"(acc[n8][2]), "+f"(acc[n8][3])
                    : "r"(a0), "r"(a1), "r"(a2), "r"(a3), "r"(b0), "r"(b1));
            }
        }

        // epilogue for this half: bias + relu
#pragma unroll
        for (int n8 = 0; n8 < 8; n8++) {
            int col = (half * 8 + n8) * 8 + (lane & 3) * 2;
            float2 bb = *reinterpret_cast<const float2*>(&b[col]);
            if (rA < N_NODES) {
                float2 v = make_float2(fmaxf(acc[n8][0] + bb.x, 0.f),
                                       fmaxf(acc[n8][1] + bb.y, 0.f));
                *reinterpret_cast<float2*>(&out[(size_t)rA * D + col]) = v;
            }
            if (rB < N_NODES) {
                float2 v = make_float2(fmaxf(acc[n8][2] + bb.x, 0.f),
                                       fmaxf(acc[n8][3] + bb.y, 0.f));
                *reinterpret_cast<float2*>(&out[(size_t)rB * D + col]) = v;
            }
        }
    }
}

// ---------------------------------------------------------------------------
// Launch. Inputs: edge_list [800000,2] i32, x [50000,128] f32,
//                 W [128,128] f32, b [128] f32. Output f32 [50000,128].
// ---------------------------------------------------------------------------
extern "C" void kernel_launch(void* const* d_in, const int* in_sizes, int n_in,
                              void* d_out, int out_size) {
    const int4*  epairs = (const int4*) d_in[0];
    const float* x      = (const float*)d_in[1];
    const float* Wm     = (const float*)d_in[2];
    const float* b      = (const float*)d_in[3];
    float* out = (float*)d_out;

    static bool attr_done = false;
    if (!attr_done) {
        cudaFuncSetAttribute(fused_kernel,
                             cudaFuncAttributeMaxDynamicSharedMemorySize,
                             SMEM_BYTES);
        attr_done = true;
    }

    zero_kernel<<<ZB + WB, 256>>>(Wm);
    degree_kernel<<<EPB, 256>>>(epairs);
    scale_scanA_kernel<<<SB + ZB, 256>>>(x);
    scanBC_kernel<<<ZB, 256>>>();
    fill_kernel<<<EPB, 256>>>(epairs);
    fused_kernel<<<(N_NODES + GEMM_ROWS - 1) / GEMM_ROWS, 256, SMEM_BYTES>>>(b, out);
}

// round 16
// speedup vs baseline: 1.1050x; 1.1050x over previous
#include <cuda_runtime.h>
#include <cuda_fp16.h>
#include <cstdint>

#define N_NODES 50000
#define N_EDGES 800000
#define D 128
#define SU 136      // padded smem stride in halves

// ---------------------------------------------------------------------------
// Device scratch
// ---------------------------------------------------------------------------
__device__ int     g_cin[N_NODES];        // deg_in  - 1 (src counts)
__device__ int     g_cnt[N_NODES];        // deg_out - 1 (dst counts)
__device__ int     g_rowptr[N_NODES + 1];
__device__ int     g_cursor[N_NODES];
__device__ int     g_col[N_EDGES];
__device__ float   g_sout[N_NODES];       // rsqrt(deg_out)
__device__ __half  g_xsh[N_NODES * D];    // fp16( x * rsqrt(deg_in) )
__device__ __half  g_Wh[D * D];           // fp16(W), [j][k] row-major
__device__ int     g_bsum[256];           // per-block count sums (196 used)

#define ZB ((N_NODES + 255) / 256)        // 196
#define EPB ((N_EDGES / 2 + 255) / 256)   // 1563 edge-pair blocks
#define WB ((D * D + 255) / 256)          // 64
#define SB ((N_NODES * (D / 4) + 255) / 256)  // 6250

__device__ __forceinline__ uint32_t smem_u32(const void* p) {
    uint32_t a;
    asm("{ .reg .u64 t; cvta.to.shared.u64 t, %1; cvt.u32.u64 %0, t; }"
        : "=r"(a) : "l"(p));
    return a;
}

// Block-wide inclusive scan (256 threads) with warp shuffles; 2 barriers.
__device__ __forceinline__ int block_incl_scan256(int v, int* ws) {
    int lane = threadIdx.x & 31, w = threadIdx.x >> 5;
#pragma unroll
    for (int o = 1; o < 32; o <<= 1) {
        int t = __shfl_up_sync(0xffffffffu, v, o);
        if (lane >= o) v += t;
    }
    if (lane == 31) ws[w] = v;
    __syncthreads();
    if (w == 0) {
        int s = (lane < 8) ? ws[lane] : 0;
#pragma unroll
        for (int o = 1; o < 8; o <<= 1) {
            int t = __shfl_up_sync(0xffffffffu, s, o);
            if (lane >= o) s += t;
        }
        if (lane < 8) ws[lane] = s;
    }
    __syncthreads();
    if (w > 0) v += ws[w - 1];
    return v;
}

// ---------------------------------------------------------------------------
// Kernel 1: zero degree counters + fp16 W convert (disjoint block ranges)
// ---------------------------------------------------------------------------
__global__ __launch_bounds__(256) void zero_kernel(const float* __restrict__ Wm) {
    int bid = blockIdx.x;
    if (bid < ZB) {
        int i = bid * 256 + threadIdx.x;
        if (i < N_NODES) { g_cin[i] = 0; g_cnt[i] = 0; }
    } else {
        int i = (bid - ZB) * 256 + threadIdx.x;
        if (i < D * D) g_Wh[i] = __float2half(Wm[i]);
    }
}

// ---------------------------------------------------------------------------
// Kernel 2: degree counts, 2 edges per thread (int4)
// ---------------------------------------------------------------------------
__global__ __launch_bounds__(256) void degree_kernel(const int4* __restrict__ epairs) {
    int i = blockIdx.x * 256 + threadIdx.x;       // pair index
    if (i < N_EDGES / 2) {
        int4 p = epairs[i];
        atomicAdd(&g_cin[p.x], 1);
        atomicAdd(&g_cnt[p.y], 1);
        atomicAdd(&g_cin[p.z], 1);
        atomicAdd(&g_cnt[p.w], 1);
    }
}

// ---------------------------------------------------------------------------
// Kernel 3: scanA — per-block sums of g_cnt (tiny, standalone)
// ---------------------------------------------------------------------------
__global__ __launch_bounds__(256) void scanA_kernel() {
    __shared__ int sh[8];
    int i = blockIdx.x * 256 + threadIdx.x;
    int v = (i < N_NODES) ? g_cnt[i] : 0;
    int lane = threadIdx.x & 31, warp = threadIdx.x >> 5;
#pragma unroll
    for (int o = 16; o > 0; o >>= 1) v += __shfl_down_sync(0xffffffffu, v, o);
    if (lane == 0) sh[warp] = v;
    __syncthreads();
    if (warp == 0) {
        int w = (lane < 8) ? sh[lane] : 0;
#pragma unroll
        for (int o = 4; o > 0; o >>= 1) w += __shfl_down_sync(0xffffffffu, w, o);
        if (lane == 0) g_bsum[blockIdx.x] = w;
    }
}

// ---------------------------------------------------------------------------
// Kernel 4: fused scanB+scanC, shuffle scans
// ---------------------------------------------------------------------------
__global__ __launch_bounds__(256) void scanBC_kernel() {
    __shared__ int bs[256];
    __shared__ int ws[8];
    int t = threadIdx.x;

    int bv = (t < ZB) ? g_bsum[t] : 0;
    int sc = block_incl_scan256(bv, ws);
    bs[t] = sc;
    __syncthreads();
    int boff  = (blockIdx.x > 0) ? bs[blockIdx.x - 1] : 0;
    int total = bs[ZB - 1];

    int i = blockIdx.x * 256 + t;
    int v = (i < N_NODES) ? g_cnt[i] : 0;
    int sc2 = block_incl_scan256(v, ws);
    if (i < N_NODES) {
        int p = boff + sc2 - v;       // exclusive prefix
        g_rowptr[i] = p;
        g_cursor[i] = p;
    }
    if (blockIdx.x == 0 && t == 0) g_rowptr[N_NODES] = total;
}

// ---------------------------------------------------------------------------
// Kernel 5: fill CSR + scale (disjoint block ranges; fill is atomic-bound,
// scale is bandwidth-bound -> they overlap on different resources)
// ---------------------------------------------------------------------------
__global__ __launch_bounds__(256) void fill_scale_kernel(
    const int4* __restrict__ epairs, const float* __restrict__ x) {
    int bid = blockIdx.x;
    if (bid < EPB) {
        int i = bid * 256 + threadIdx.x;       // pair index
        if (i < N_EDGES / 2) {
            int4 p = epairs[i];
            int pos0 = atomicAdd(&g_cursor[p.y], 1);
            g_col[pos0] = p.x;
            int pos1 = atomicAdd(&g_cursor[p.w], 1);
            g_col[pos1] = p.z;
        }
    } else {
        int i = (bid - EPB) * 256 + threadIdx.x;   // float4 index
        if (i < N_NODES * (D / 4)) {
            int row = i >> 5;
            float s = rsqrtf((float)(g_cin[row] + 1));
            float4 v = reinterpret_cast<const float4*>(x)[i];
            __half2 h0 = __floats2half2_rn(v.x * s, v.y * s);
            __half2 h1 = __floats2half2_rn(v.z * s, v.w * s);
            *reinterpret_cast<__half2*>(&g_xsh[(size_t)i * 4])     = h0;
            *reinterpret_cast<__half2*>(&g_xsh[(size_t)i * 4 + 2]) = h1;
            if ((i & 31) == 0) g_sout[row] = rsqrtf((float)(g_cnt[row] + 1));
        }
    }
}

// ---------------------------------------------------------------------------
// Kernel 6: FUSED gather + tensor-core GEMM (mma.sync m16n8k16 f16).
//   256 threads / 8 warps / 128 rows (16/warp, private), 3 CTAs/SM.
//   Gather: 8 edges batched per iteration (MLP 8) to halve latency stalls.
// ---------------------------------------------------------------------------
#define GEMM_ROWS 128
#define SMEM_W_HALVES (D * SU)                 // 17408
#define SMEM_U_HALVES (GEMM_ROWS * SU)         // 17408
#define SMEM_BYTES ((SMEM_W_HALVES + SMEM_U_HALVES) * 2)   // 69632

__global__ __launch_bounds__(256, 3) void fused_kernel(
    const float* __restrict__ b, float* __restrict__ out) {
    extern __shared__ __half smem[];
    __half* Ws = smem;                     // [128][SU]
    __half* Us = smem + SMEM_W_HALVES;     // [128][SU]

    int tid  = threadIdx.x;
    int lane = tid & 31;
    int warp = tid >> 5;
    int row0 = blockIdx.x * GEMM_ROWS;
    int r0   = warp * 16;                  // warp-local row base

    // ---- Stage W (coalesced uint4 = 8 halves), barrier BEFORE gather ----
    {
        const uint4* src = reinterpret_cast<const uint4*>(g_Wh);
        for (int t = tid; t < D * (D / 8); t += 256) {
            int row = t >> 4;
            int c8  = t & 15;
            uint4 v = src[t];
            *reinterpret_cast<uint4*>(&Ws[row * SU + c8 * 8]) = v;
        }
    }
    __syncthreads();

    // ---- Phase 1: warp-private gather of rows [16w, 16w+16), MLP 8 ----
    {
        const __half2* xs2 = reinterpret_cast<const __half2*>(g_xsh);
        int fo = lane * 2;                 // half2 index within row [0,64)
#pragma unroll 2
        for (int i = 0; i < 16; i++) {
            int node = row0 + r0 + i;
            float2 a0 = make_float2(0.f, 0.f);
            float2 a1 = make_float2(0.f, 0.f);
            if (node < N_NODES) {
                uint2 raw = *reinterpret_cast<const uint2*>(&xs2[(size_t)node * 64 + fo]);
                a0 = __half22float2(*reinterpret_cast<__half2*>(&raw.x));
                a1 = __half22float2(*reinterpret_cast<__half2*>(&raw.y));
                int s = g_rowptr[node];
                int e = g_rowptr[node + 1];
                int j = s;
                for (; j + 8 <= e; j += 8) {
                    int uu[8];
#pragma unroll
                    for (int m = 0; m < 8; m++) uu[m] = g_col[j + m];
                    uint2 q[8];
#pragma unroll
                    for (int m = 0; m < 8; m++)
                        q[m] = *reinterpret_cast<const uint2*>(&xs2[(size_t)uu[m] * 64 + fo]);
#pragma unroll
                    for (int m = 0; m < 8; m++) {
                        float2 f;
                        f = __half22float2(*reinterpret_cast<__half2*>(&q[m].x));
                        a0.x += f.x; a0.y += f.y;
                        f = __half22float2(*reinterpret_cast<__half2*>(&q[m].y));
                        a1.x += f.x; a1.y += f.y;
                    }
                }
                for (; j < e; j++) {
                    int u = g_col[j];
                    uint2 qq = *reinterpret_cast<const uint2*>(&xs2[(size_t)u * 64 + fo]);
                    float2 f;
                    f = __half22float2(*reinterpret_cast<__half2*>(&qq.x)); a0.x += f.x; a0.y += f.y;
                    f = __half22float2(*reinterpret_cast<__half2*>(&qq.y)); a1.x += f.x; a1.y += f.y;
                }
                float so = g_sout[node];
                a0.x *= so; a0.y *= so; a1.x *= so; a1.y *= so;
            }
            __half2 h0 = __floats2half2_rn(a0.x, a0.y);
            __half2 h1 = __floats2half2_rn(a1.x, a1.y);
            uint2 packed;
            packed.x = *reinterpret_cast<uint32_t*>(&h0);
            packed.y = *reinterpret_cast<uint32_t*>(&h1);
            *reinterpret_cast<uint2*>(&Us[(r0 + i) * SU + lane * 4]) = packed;
        }
    }
    __syncwarp();

    // ---- Phase 2: 16x128 = A(16x128) @ W^T, two 64-col halves ----
    int tr = lane & 7;
    int aRow  = r0 + tr + ((lane & 8) ? 8 : 0);
    int aKoff = (lane & 16) ? 8 : 0;
    uint32_t aBase = smem_u32(&Us[aRow * SU + aKoff]);
    int bTile = (lane >> 3) & 1;
    uint32_t bBase = smem_u32(&Ws[tr * SU + bTile * 8]);

    int rA = row0 + r0 + (lane >> 2);
    int rB = rA + 8;

#pragma unroll
    for (int half = 0; half < 2; half++) {
        float acc[8][4];
#pragma unroll
        for (int n8 = 0; n8 < 8; n8++)
#pragma unroll
            for (int q = 0; q < 4; q++) acc[n8][q] = 0.f;

#pragma unroll
        for (int ks = 0; ks < 8; ks++) {        // k = 16*ks
            uint32_t a0, a1, a2, a3;
            asm volatile(
                "ldmatrix.sync.aligned.m8n8.x4.shared.b16 {%0,%1,%2,%3}, [%4];"
                : "=r"(a0), "=r"(a1), "=r"(a2), "=r"(a3)
                : "r"(aBase + ks * 32));
#pragma unroll
            for (int n8 = 0; n8 < 8; n8++) {
                int nt = half * 8 + n8;
                uint32_t b0, b1;
                asm volatile(
                    "ldmatrix.sync.aligned.m8n8.x2.shared.b16 {%0,%1}, [%2];"
                    : "=r"(b0), "=r"(b1)
                    : "r"(bBase + nt * (8 * SU * 2) + ks * 32));
                asm volatile(
                    "mma.sync.aligned.m16n8k16.row.col.f32.f16.f16.f32 "
                    "{%0,%1,%2,%3}, {%4,%5,%6,%7}, {%8,%9}, {%0,%1,%2,%3};"
                    : "+f"(acc[n8][0]), "+f"(acc[n8][1]),
                      "+f"(acc[n8][2]), "+f"(acc[n8][3])
                    : "r"(a0), "r"(a1), "r"(a2), "r"(a3), "r"(b0), "r"(b1));
            }
        }

        // epilogue for this half: bias + relu
#pragma unroll
        for (int n8 = 0; n8 < 8; n8++) {
            int col = (half * 8 + n8) * 8 + (lane & 3) * 2;
            float2 bb = *reinterpret_cast<const float2*>(&b[col]);
            if (rA < N_NODES) {
                float2 v = make_float2(fmaxf(acc[n8][0] + bb.x, 0.f),
                                       fmaxf(acc[n8][1] + bb.y, 0.f));
                *reinterpret_cast<float2*>(&out[(size_t)rA * D + col]) = v;
            }
            if (rB < N_NODES) {
                float2 v = make_float2(fmaxf(acc[n8][2] + bb.x, 0.f),
                                       fmaxf(acc[n8][3] + bb.y, 0.f));
                *reinterpret_cast<float2*>(&out[(size_t)rB * D + col]) = v;
            }
        }
    }
}

// ---------------------------------------------------------------------------
// Launch. Inputs: edge_list [800000,2] i32, x [50000,128] f32,
//                 W [128,128] f32, b [128] f32. Output f32 [50000,128].
// ---------------------------------------------------------------------------
extern "C" void kernel_launch(void* const* d_in, const int* in_sizes, int n_in,
                              void* d_out, int out_size) {
    const int4*  epairs = (const int4*) d_in[0];
    const float* x      = (const float*)d_in[1];
    const float* Wm     = (const float*)d_in[2];
    const float* b      = (const float*)d_in[3];
    float* out = (float*)d_out;

    static bool attr_done = false;
    if (!attr_done) {
        cudaFuncSetAttribute(fused_kernel,
                             cudaFuncAttributeMaxDynamicSharedMemorySize,
                             SMEM_BYTES);
        attr_done = true;
    }

    zero_kernel<<<ZB + WB, 256>>>(Wm);
    degree_kernel<<<EPB, 256>>>(epairs);
    scanA_kernel<<<ZB, 256>>>();
    scanBC_kernel<<<ZB, 256>>>();
    fill_scale_kernel<<<EPB + SB, 256>>>(epairs, x);
    fused_kernel<<<(N_NODES + GEMM_ROWS - 1) / GEMM_ROWS, 256, SMEM_BYTES>>>(b, out);
}